// round 6
// baseline (speedup 1.0000x reference)
#include <cuda_runtime.h>
#include <cstdint>

#define N_NODES   100000
#define N_EDGES   1600000
#define IN_FEATS  64
#define OUT_FEATS 32
#define NODE_PAIRS (N_NODES / 2)

#define GEMM_BLOCKS  782            // ceil(200000/256)
#define COUNT_BLOCKS 218
#define SCAN_BLOCKS  391            // ceil(100000/256)

// Scratch (no cudaMalloc allowed)
__device__ float g_hW[N_NODES * OUT_FEATS];      // 12.8 MB
__device__ int   g_cnt[N_NODES];                 // histogram
__device__ int   g_pre[N_NODES];                 // block-local exclusive prescan
__device__ int   g_bsum[SCAN_BLOCKS];            // block sums
__device__ int   g_bsum_ex[SCAN_BLOCKS];         // exclusive-scanned block sums
__device__ int   g_off[N_NODES + 1];             // final bin offsets
__device__ int   g_pos[N_NODES];                 // running fill positions
__device__ uint2 g_erec[N_EDGES];                // binned (src, order) records

// ---------------------------------------------------------------------------
// K0: zero histogram
// ---------------------------------------------------------------------------
__global__ void zero_cnt_kernel() {
    int i = blockIdx.x * blockDim.x + threadIdx.x;
    if (i < N_NODES) g_cnt[i] = 0;
}

// ---------------------------------------------------------------------------
// K1: block-specialized:  blocks [0,GEMM_BLOCKS) -> hW = h @ W
//                         blocks [GEMM_BLOCKS, ..) -> dst histogram
// gemm: 2-node x 8-feature register tile per thread (round-5 layout).
// ---------------------------------------------------------------------------
__global__ void __launch_bounds__(256) gemm_count_kernel(
        const float* __restrict__ h,
        const float* __restrict__ W,
        const int*   __restrict__ dst) {
    if (blockIdx.x >= GEMM_BLOCKS) {
        // histogram blocks: grid-stride over edges
        int e0     = (blockIdx.x - GEMM_BLOCKS) * blockDim.x + threadIdx.x;
        int stride = COUNT_BLOCKS * blockDim.x;
        for (int e = e0; e < N_EDGES; e += stride)
            atomicAdd(g_cnt + __ldg(dst + e), 1);
        return;
    }

    __shared__ float4 sW4[IN_FEATS * OUT_FEATS / 4];   // 8 KB, [k][j]
    {
        const float4* W4 = reinterpret_cast<const float4*>(W);
        for (int i = threadIdx.x; i < IN_FEATS * OUT_FEATS / 4; i += blockDim.x)
            sW4[i] = W4[i];
    }
    __syncthreads();

    int t  = blockIdx.x * blockDim.x + threadIdx.x;
    int np = t >> 2;
    int jg = t & 3;
    if (np >= NODE_PAIRS) return;

    int node0 = np * 2;
    const float* hbase = h + (size_t)node0 * IN_FEATS;

    float acc[2][8];
    #pragma unroll
    for (int i = 0; i < 2; i++)
        #pragma unroll
        for (int j = 0; j < 8; j++) acc[i][j] = 0.0f;

    #pragma unroll 4
    for (int k4 = 0; k4 < IN_FEATS / 4; k4++) {
        float4 hv[2];
        hv[0] = __ldg(reinterpret_cast<const float4*>(hbase + k4 * 4));
        hv[1] = __ldg(reinterpret_cast<const float4*>(hbase + IN_FEATS + k4 * 4));

        #pragma unroll
        for (int kk = 0; kk < 4; kk++) {
            int k = k4 * 4 + kk;
            float4 w0 = sW4[k * (OUT_FEATS / 4) + jg * 2 + 0];
            float4 w1 = sW4[k * (OUT_FEATS / 4) + jg * 2 + 1];
            #pragma unroll
            for (int i = 0; i < 2; i++) {
                float hk = (kk == 0) ? hv[i].x : (kk == 1) ? hv[i].y
                         : (kk == 2) ? hv[i].z : hv[i].w;
                acc[i][0] = fmaf(hk, w0.x, acc[i][0]);
                acc[i][1] = fmaf(hk, w0.y, acc[i][1]);
                acc[i][2] = fmaf(hk, w0.z, acc[i][2]);
                acc[i][3] = fmaf(hk, w0.w, acc[i][3]);
                acc[i][4] = fmaf(hk, w1.x, acc[i][4]);
                acc[i][5] = fmaf(hk, w1.y, acc[i][5]);
                acc[i][6] = fmaf(hk, w1.z, acc[i][6]);
                acc[i][7] = fmaf(hk, w1.w, acc[i][7]);
            }
        }
    }

    #pragma unroll
    for (int i = 0; i < 2; i++) {
        float4* orow = reinterpret_cast<float4*>(
            g_hW + (size_t)(node0 + i) * OUT_FEATS + jg * 8);
        orow[0] = make_float4(acc[i][0], acc[i][1], acc[i][2], acc[i][3]);
        orow[1] = make_float4(acc[i][4], acc[i][5], acc[i][6], acc[i][7]);
    }
}

// ---------------------------------------------------------------------------
// K2: per-block inclusive scan (256/block) -> exclusive prescan + block sums
// ---------------------------------------------------------------------------
__global__ void __launch_bounds__(256) scan1_kernel() {
    __shared__ int s[256];
    int tid = threadIdx.x;
    int i   = blockIdx.x * 256 + tid;
    int c   = (i < N_NODES) ? g_cnt[i] : 0;
    s[tid] = c;
    __syncthreads();
    #pragma unroll
    for (int off = 1; off < 256; off <<= 1) {
        int v = (tid >= off) ? s[tid - off] : 0;
        __syncthreads();
        s[tid] += v;
        __syncthreads();
    }
    if (i < N_NODES) g_pre[i] = s[tid] - c;
    if (tid == 255)  g_bsum[blockIdx.x] = s[tid];
}

// ---------------------------------------------------------------------------
// K3: single-block exclusive scan of block sums (SCAN_BLOCKS <= 512)
// ---------------------------------------------------------------------------
__global__ void __launch_bounds__(512) scan2_kernel() {
    __shared__ int s[512];
    int tid = threadIdx.x;
    int c   = (tid < SCAN_BLOCKS) ? g_bsum[tid] : 0;
    s[tid] = c;
    __syncthreads();
    #pragma unroll
    for (int off = 1; off < 512; off <<= 1) {
        int v = (tid >= off) ? s[tid - off] : 0;
        __syncthreads();
        s[tid] += v;
        __syncthreads();
    }
    if (tid < SCAN_BLOCKS) g_bsum_ex[tid] = s[tid] - c;
}

// ---------------------------------------------------------------------------
// K4: final offsets + running positions
// ---------------------------------------------------------------------------
__global__ void __launch_bounds__(256) scan3_kernel() {
    int tid = threadIdx.x;
    int i   = blockIdx.x * 256 + tid;
    if (i < N_NODES) {
        int o = g_pre[i] + g_bsum_ex[blockIdx.x];
        g_off[i] = o;
        g_pos[i] = o;
    }
    if (i == 0) g_off[N_NODES] = N_EDGES;
}

// ---------------------------------------------------------------------------
// K5: reorder edges into dst bins: g_erec[pos] = (src, order_bits)
// ---------------------------------------------------------------------------
__global__ void __launch_bounds__(256) reorder_kernel(
        const int*   __restrict__ src,
        const int*   __restrict__ dst,
        const float* __restrict__ order) {
    int e = blockIdx.x * blockDim.x + threadIdx.x;
    if (e >= N_EDGES) return;
    int d = __ldg(dst + e);
    int p = atomicAdd(g_pos + d, 1);
    g_erec[p] = make_uint2((unsigned)__ldg(src + e),
                           __float_as_uint(__ldg(order + e)));
}

// ---------------------------------------------------------------------------
// K6: gather + normalize + bias + relu. 8 lanes per dst node, each owning
// 4 feature floats. No atomics: accumulate in registers, single store.
// ---------------------------------------------------------------------------
__global__ void __launch_bounds__(256) gather_kernel(
        float*       __restrict__ out,
        const float* __restrict__ b) {
    int t   = blockIdx.x * blockDim.x + threadIdx.x;
    int g   = t >> 3;        // dst node
    int sub = t & 7;         // 4-float slice
    if (g >= N_NODES) return;

    int start = __ldg(g_off + g);
    int end   = __ldg(g_off + g + 1);

    const float4* hW4 = reinterpret_cast<const float4*>(g_hW);

    float4 acc = make_float4(0.f, 0.f, 0.f, 0.f);
    int p = start;
    for (; p + 2 <= end; p += 2) {
        uint2 r0 = g_erec[p];
        uint2 r1 = g_erec[p + 1];
        float4 v0 = __ldg(hW4 + (size_t)r0.x * 8 + sub);
        float4 v1 = __ldg(hW4 + (size_t)r1.x * 8 + sub);
        float  w0 = __uint_as_float(r0.y);
        float  w1 = __uint_as_float(r1.y);
        acc.x = fmaf(w0, v0.x, acc.x); acc.y = fmaf(w0, v0.y, acc.y);
        acc.z = fmaf(w0, v0.z, acc.z); acc.w = fmaf(w0, v0.w, acc.w);
        acc.x = fmaf(w1, v1.x, acc.x); acc.y = fmaf(w1, v1.y, acc.y);
        acc.z = fmaf(w1, v1.z, acc.z); acc.w = fmaf(w1, v1.w, acc.w);
    }
    if (p < end) {
        uint2 r0 = g_erec[p];
        float4 v0 = __ldg(hW4 + (size_t)r0.x * 8 + sub);
        float  w0 = __uint_as_float(r0.y);
        acc.x = fmaf(w0, v0.x, acc.x); acc.y = fmaf(w0, v0.y, acc.y);
        acc.z = fmaf(w0, v0.z, acc.z); acc.w = fmaf(w0, v0.w, acc.w);
    }

    float norm = 1.0f / fmaxf((float)(end - start), 1.0f);
    float4 bb  = __ldg(reinterpret_cast<const float4*>(b) + sub);

    float4 r;
    r.x = fmaxf(fmaf(acc.x, norm, bb.x), 0.0f);
    r.y = fmaxf(fmaf(acc.y, norm, bb.y), 0.0f);
    r.z = fmaxf(fmaf(acc.z, norm, bb.z), 0.0f);
    r.w = fmaxf(fmaf(acc.w, norm, bb.w), 0.0f);
    reinterpret_cast<float4*>(out)[(size_t)g * 8 + sub] = r;
}

// ---------------------------------------------------------------------------
// Launch
// ---------------------------------------------------------------------------
extern "C" void kernel_launch(void* const* d_in, const int* in_sizes, int n_in,
                              void* d_out, int out_size) {
    const float* h     = (const float*)d_in[0];
    const int*   src   = (const int*)  d_in[1];
    const int*   dst   = (const int*)  d_in[2];
    const float* order = (const float*)d_in[3];
    const float* W     = (const float*)d_in[4];
    const float* b     = (const float*)d_in[5];
    float*       out   = (float*)d_out;

    (void)in_sizes; (void)n_in; (void)out_size;

    zero_cnt_kernel<<<(N_NODES + 255) / 256, 256>>>();

    gemm_count_kernel<<<GEMM_BLOCKS + COUNT_BLOCKS, 256>>>(h, W, dst);

    scan1_kernel<<<SCAN_BLOCKS, 256>>>();
    scan2_kernel<<<1, 512>>>();
    scan3_kernel<<<SCAN_BLOCKS, 256>>>();

    reorder_kernel<<<(N_EDGES + 255) / 256, 256>>>(src, dst, order);

    gather_kernel<<<(N_NODES * 8 + 255) / 256, 256>>>(out, b);
}